// round 2
// baseline (speedup 1.0000x reference)
#include <cuda_runtime.h>

#define B_  8
#define S_  1024
#define H_  1024
#define NH_ 16
#define HD_ 64
#define MROWS (B_ * S_)

// Scratch: Q, K, V projections and attention output (each 32 MB).
__device__ float g_Q[MROWS * H_];
__device__ float g_K[MROWS * H_];
__device__ float g_V[MROWS * H_];
__device__ float g_A[MROWS * H_];

// ---------------------------------------------------------------------------
// GEMM: C[m,n] = sum_k A[m,k] * W[n,k] + bias[n]
// A: (M=8192, K=1024) row-major. W: (N=1024, K=1024) row-major (einsum 'bsh,oh->bso').
// 128x128 block tile, 8x8 micro-tile, BK=8, 256 threads.
// ---------------------------------------------------------------------------
__global__ __launch_bounds__(256, 2)
void gemm_atb(const float* __restrict__ A, const float* __restrict__ W,
              const float* __restrict__ bias, float* __restrict__ C)
{
    const int K = H_;
    const int N = H_;
    __shared__ float As[8][128];
    __shared__ float Ws[8][128];

    const int tid = threadIdx.x;
    const int bm0 = blockIdx.y * 128;
    const int bn0 = blockIdx.x * 128;
    const int tx  = (tid & 15) * 8;   // n offset within tile
    const int ty  = (tid >> 4) * 8;   // m offset within tile

    float acc[8][8];
#pragma unroll
    for (int i = 0; i < 8; i++)
#pragma unroll
        for (int j = 0; j < 8; j++) acc[i][j] = 0.f;

    const int ldRow = tid >> 1;          // 0..127
    const int ldCol = (tid & 1) * 4;     // 0 or 4
    const float* Ap = A + (size_t)(bm0 + ldRow) * K + ldCol;
    const float* Wp = W + (size_t)(bn0 + ldRow) * K + ldCol;

    for (int k0 = 0; k0 < K; k0 += 8) {
        float4 a4 = *(const float4*)(Ap + k0);
        float4 w4 = *(const float4*)(Wp + k0);
        As[ldCol + 0][ldRow] = a4.x;
        As[ldCol + 1][ldRow] = a4.y;
        As[ldCol + 2][ldRow] = a4.z;
        As[ldCol + 3][ldRow] = a4.w;
        Ws[ldCol + 0][ldRow] = w4.x;
        Ws[ldCol + 1][ldRow] = w4.y;
        Ws[ldCol + 2][ldRow] = w4.z;
        Ws[ldCol + 3][ldRow] = w4.w;
        __syncthreads();
#pragma unroll
        for (int k = 0; k < 8; k++) {
            float ra[8], rb[8];
            *(float4*)&ra[0] = *(const float4*)&As[k][ty];
            *(float4*)&ra[4] = *(const float4*)&As[k][ty + 4];
            *(float4*)&rb[0] = *(const float4*)&Ws[k][tx];
            *(float4*)&rb[4] = *(const float4*)&Ws[k][tx + 4];
#pragma unroll
            for (int i = 0; i < 8; i++)
#pragma unroll
                for (int j = 0; j < 8; j++)
                    acc[i][j] += ra[i] * rb[j];
        }
        __syncthreads();
    }

#pragma unroll
    for (int i = 0; i < 8; i++) {
        const int row = bm0 + ty + i;
        float* cp = C + (size_t)row * N + bn0 + tx;
#pragma unroll
        for (int j = 0; j < 8; j += 4) {
            float4 o;
            o.x = acc[i][j + 0] + bias[bn0 + tx + j + 0];
            o.y = acc[i][j + 1] + bias[bn0 + tx + j + 1];
            o.z = acc[i][j + 2] + bias[bn0 + tx + j + 2];
            o.w = acc[i][j + 3] + bias[bn0 + tx + j + 3];
            *(float4*)(cp + j) = o;
        }
    }
}

// ---------------------------------------------------------------------------
// Flash-style attention. One block per (b, head, 64-row q-tile). 64 threads,
// each thread owns one q row entirely in registers. Online softmax.
// mask is int32 (bool upcast by the harness): nonzero -> key masked out
// (reference adds -1e32 -> weight exactly 0), so we skip those keys.
// Scale = 1/sqrt(H) = 1/32.
// ---------------------------------------------------------------------------
__global__ __launch_bounds__(64)
void attn_kernel(const float* __restrict__ Q, const float* __restrict__ Km,
                 const float* __restrict__ Vm,
                 const int* __restrict__ mask,
                 float* __restrict__ O)
{
    __shared__ float4 Ks[64][16];
    __shared__ float4 Vs[64][16];
    __shared__ int ms[64];

    const int t  = threadIdx.x;        // 0..63
    const int qt = blockIdx.x;         // q tile (16)
    const int h  = blockIdx.y;         // head (16)
    const int b  = blockIdx.z;         // batch (8)
    const int hb = h * HD_;
    const int qr = qt * 64 + t;

    const float4* qp = (const float4*)(Q + ((size_t)(b * S_ + qr)) * H_ + hb);
    float4 q[16];
#pragma unroll
    for (int c = 0; c < 16; c++) q[c] = qp[c];

    float4 acc[16];
#pragma unroll
    for (int c = 0; c < 16; c++) acc[c] = make_float4(0.f, 0.f, 0.f, 0.f);
    float mmax = -3.0e38f;
    float l = 0.f;

    for (int kt = 0; kt < S_; kt += 64) {
        const float4* kp = (const float4*)(Km + ((size_t)(b * S_ + kt)) * H_ + hb);
        const float4* vp = (const float4*)(Vm + ((size_t)(b * S_ + kt)) * H_ + hb);
        // 64 rows x 16 float4 per tile; 64 threads -> 16 loads each.
#pragma unroll
        for (int i = 0; i < 16; i++) {
            int idx = t + i * 64;
            int r = idx >> 4, c = idx & 15;
            Ks[r][c] = kp[(size_t)r * (H_ / 4) + c];
            Vs[r][c] = vp[(size_t)r * (H_ / 4) + c];
        }
        ms[t] = mask[(size_t)b * S_ + kt + t];
        __syncthreads();

        for (int kk = 0; kk < 64; kk++) {
            if (ms[kk]) continue;          // masked key -> weight 0
            float4 s4 = make_float4(0.f, 0.f, 0.f, 0.f);
#pragma unroll
            for (int c = 0; c < 16; c++) {
                float4 kv = Ks[kk][c];
                s4.x += q[c].x * kv.x;
                s4.y += q[c].y * kv.y;
                s4.z += q[c].z * kv.z;
                s4.w += q[c].w * kv.w;
            }
            float s = (s4.x + s4.y + s4.z + s4.w) * 0.03125f;
            float p;
            if (s > mmax) {
                float f = __expf(mmax - s);
                l = l * f + 1.f;
#pragma unroll
                for (int c = 0; c < 16; c++) {
                    acc[c].x *= f; acc[c].y *= f; acc[c].z *= f; acc[c].w *= f;
                }
                mmax = s;
                p = 1.f;
            } else {
                p = __expf(s - mmax);
                l += p;
            }
#pragma unroll
            for (int c = 0; c < 16; c++) {
                float4 vv = Vs[kk][c];
                acc[c].x += p * vv.x;
                acc[c].y += p * vv.y;
                acc[c].z += p * vv.z;
                acc[c].w += p * vv.w;
            }
        }
        __syncthreads();
    }

    const float rl = 1.f / l;
    float4* op = (float4*)(O + ((size_t)(b * S_ + qr)) * H_ + hb);
#pragma unroll
    for (int c = 0; c < 16; c++) {
        float4 o;
        o.x = acc[c].x * rl;
        o.y = acc[c].y * rl;
        o.z = acc[c].z * rl;
        o.w = acc[c].w * rl;
        op[c] = o;
    }
}

// ---------------------------------------------------------------------------
// Launch. Input order (metadata): query, key, value, mask, [seq_mask],
// Wq, bq, Wk, bk, Wv, bv, Wo, bo. seq_mask == 0 -> no causal mask; it may or
// may not be materialized as a device input, so index weights off n_in.
// ---------------------------------------------------------------------------
extern "C" void kernel_launch(void* const* d_in, const int* in_sizes, int n_in,
                              void* d_out, int out_size)
{
    const float* query = (const float*)d_in[0];
    const float* key   = (const float*)d_in[1];
    const float* value = (const float*)d_in[2];
    const int*   mask  = (const int*)d_in[3];

    // Weights start right after (mask, [seq_mask]).
    const int wb = (n_in >= 13) ? 5 : 4;
    const float* Wq = (const float*)d_in[wb + 0];
    const float* bq = (const float*)d_in[wb + 1];
    const float* Wk = (const float*)d_in[wb + 2];
    const float* bk = (const float*)d_in[wb + 3];
    const float* Wv = (const float*)d_in[wb + 4];
    const float* bv = (const float*)d_in[wb + 5];
    const float* Wo = (const float*)d_in[wb + 6];
    const float* bo = (const float*)d_in[wb + 7];
    float* out = (float*)d_out;

    float *dQ, *dK, *dV, *dA;
    cudaGetSymbolAddress((void**)&dQ, g_Q);
    cudaGetSymbolAddress((void**)&dK, g_K);
    cudaGetSymbolAddress((void**)&dV, g_V);
    cudaGetSymbolAddress((void**)&dA, g_A);

    dim3 ggrid(H_ / 128, MROWS / 128);   // (8, 64)
    gemm_atb<<<ggrid, 256>>>(query, Wq, bq, dQ);
    gemm_atb<<<ggrid, 256>>>(key,   Wk, bk, dK);
    gemm_atb<<<ggrid, 256>>>(value, Wv, bv, dV);

    dim3 agrid(S_ / 64, NH_, B_);        // (16, 16, 8)
    attn_kernel<<<agrid, 64>>>(dQ, dK, dV, mask, dA);

    gemm_atb<<<ggrid, 256>>>(dA, Wo, bo, out);
}

// round 4
// speedup vs baseline: 1.7931x; 1.7931x over previous
#include <cuda_runtime.h>
#include <cuda_bf16.h>
#include <cstdint>

#define B_  8
#define S_  1024
#define H_  1024
#define NH_ 16
#define HD_ 64
#define MROWS (B_ * S_)

// Scratch: Q, K, V projections and attention output (each 32 MB).
__device__ float g_Q[MROWS * H_];
__device__ float g_K[MROWS * H_];
__device__ float g_V[MROWS * H_];
__device__ float g_A[MROWS * H_];

__device__ __forceinline__ uint32_t smem_u32(const void* p) {
    uint32_t a;
    asm("{ .reg .u64 t; cvta.to.shared.u64 t, %1; cvt.u32.u64 %0, t; }"
        : "=r"(a) : "l"(p));
    return a;
}

#define LDMX4(r0, r1, r2, r3, addr) \
    asm volatile("ldmatrix.sync.aligned.m8n8.x4.shared.b16 {%0,%1,%2,%3}, [%4];" \
                 : "=r"(r0), "=r"(r1), "=r"(r2), "=r"(r3) : "r"(addr))

#define MMA16816(d, a, b) \
    asm volatile("mma.sync.aligned.m16n8k16.row.col.f32.bf16.bf16.f32 " \
                 "{%0,%1,%2,%3}, {%4,%5,%6,%7}, {%8,%9}, {%0,%1,%2,%3};" \
                 : "+f"((d)[0]), "+f"((d)[1]), "+f"((d)[2]), "+f"((d)[3]) \
                 : "r"((a)[0]), "r"((a)[1]), "r"((a)[2]), "r"((a)[3]), \
                   "r"((b)[0]), "r"((b)[1]))

// ===========================================================================
// bf16 mma.sync split-precision GEMM: C[m,n] = sum_k A[m,k]*W[n,k] + bias[n]
// A: (8192,1024) fp32 K-major. W: (1024,1024) fp32 K-major.
// 128x128 tile, BK=32, 8 warps (2x4), warp tile 64x32.
// 3-term split: Ah*Wh + Al*Wh + Ah*Wl with fp32 accum.
// ===========================================================================
#define LDSROW 40   // bf16 elems per smem row (32 + 8 pad) -> 80 bytes

__global__ __launch_bounds__(256, 1)
void gemm_tc(const float* __restrict__ A, const float* __restrict__ W,
             const float* __restrict__ bias, float* __restrict__ C)
{
    __shared__ __nv_bfloat16 sAh[128 * LDSROW];
    __shared__ __nv_bfloat16 sAl[128 * LDSROW];
    __shared__ __nv_bfloat16 sWh[128 * LDSROW];
    __shared__ __nv_bfloat16 sWl[128 * LDSROW];

    const int tid  = threadIdx.x;
    const int wid  = tid >> 5;
    const int lane = tid & 31;
    const int wm   = wid & 1;          // 2 warp-rows of 64
    const int wn   = wid >> 1;         // 4 warp-cols of 32
    const int bm0  = blockIdx.y * 128;
    const int bn0  = blockIdx.x * 128;

    const uint32_t bAh = smem_u32(sAh);
    const uint32_t bAl = smem_u32(sAl);
    const uint32_t bWh = smem_u32(sWh);
    const uint32_t bWl = smem_u32(sWl);

    // ldmatrix lane offsets
    const uint32_t aLOff = (uint32_t)((wm * 64 + (lane & 15)) * (LDSROW * 2) + (lane >> 4) * 16);
    const uint32_t bLOff = (uint32_t)((wn * 32 + ((lane >> 4) & 1) * 8 + (lane & 7)) * (LDSROW * 2)
                                      + ((lane >> 3) & 1) * 16);

    // global load slots: 4 per operand; slot -> row = slot>>3, c4 = slot&7
    int gRow[4], gC4[4];
#pragma unroll
    for (int i = 0; i < 4; i++) { int s = tid + i * 256; gRow[i] = s >> 3; gC4[i] = s & 7; }

    float acc[4][4][4];
#pragma unroll
    for (int mi = 0; mi < 4; mi++)
#pragma unroll
        for (int nj = 0; nj < 4; nj++)
#pragma unroll
            for (int e = 0; e < 4; e++) acc[mi][nj][e] = 0.f;

    float4 ra[4], rw[4];
    // prologue: load chunk 0
#pragma unroll
    for (int i = 0; i < 4; i++) {
        ra[i] = *(const float4*)(A + (size_t)(bm0 + gRow[i]) * H_ + gC4[i] * 4);
        rw[i] = *(const float4*)(W + (size_t)(bn0 + gRow[i]) * H_ + gC4[i] * 4);
    }

    for (int c = 0; c < 32; c++) {
        // stage current chunk into smem (hi/lo split)
#pragma unroll
        for (int i = 0; i < 4; i++) {
            const int off = gRow[i] * LDSROW + gC4[i] * 4;
            float4 a4 = ra[i], w4 = rw[i];
            __nv_bfloat162 ah01 = __float22bfloat162_rn(make_float2(a4.x, a4.y));
            __nv_bfloat162 ah23 = __float22bfloat162_rn(make_float2(a4.z, a4.w));
            __nv_bfloat162 al01 = __float22bfloat162_rn(make_float2(
                a4.x - __bfloat162float(ah01.x), a4.y - __bfloat162float(ah01.y)));
            __nv_bfloat162 al23 = __float22bfloat162_rn(make_float2(
                a4.z - __bfloat162float(ah23.x), a4.w - __bfloat162float(ah23.y)));
            *(__nv_bfloat162*)(sAh + off)     = ah01;
            *(__nv_bfloat162*)(sAh + off + 2) = ah23;
            *(__nv_bfloat162*)(sAl + off)     = al01;
            *(__nv_bfloat162*)(sAl + off + 2) = al23;

            __nv_bfloat162 wh01 = __float22bfloat162_rn(make_float2(w4.x, w4.y));
            __nv_bfloat162 wh23 = __float22bfloat162_rn(make_float2(w4.z, w4.w));
            __nv_bfloat162 wl01 = __float22bfloat162_rn(make_float2(
                w4.x - __bfloat162float(wh01.x), w4.y - __bfloat162float(wh01.y)));
            __nv_bfloat162 wl23 = __float22bfloat162_rn(make_float2(
                w4.z - __bfloat162float(wh23.x), w4.w - __bfloat162float(wh23.y)));
            *(__nv_bfloat162*)(sWh + off)     = wh01;
            *(__nv_bfloat162*)(sWh + off + 2) = wh23;
            *(__nv_bfloat162*)(sWl + off)     = wl01;
            *(__nv_bfloat162*)(sWl + off + 2) = wl23;
        }
        __syncthreads();

        // prefetch next chunk (global -> regs) while mma runs
        if (c < 31) {
            const int k0 = (c + 1) * 32;
#pragma unroll
            for (int i = 0; i < 4; i++) {
                ra[i] = *(const float4*)(A + (size_t)(bm0 + gRow[i]) * H_ + k0 + gC4[i] * 4);
                rw[i] = *(const float4*)(W + (size_t)(bn0 + gRow[i]) * H_ + k0 + gC4[i] * 4);
            }
        }

        // compute: 2 k16 steps
#pragma unroll
        for (int ks = 0; ks < 2; ks++) {
            const uint32_t kb = (uint32_t)(ks * 32);
            uint32_t ah[4][4], al[4][4];
#pragma unroll
            for (int mi = 0; mi < 4; mi++) {
                const uint32_t rowb = (uint32_t)(mi * 16 * LDSROW * 2) + aLOff + kb;
                LDMX4(ah[mi][0], ah[mi][1], ah[mi][2], ah[mi][3], bAh + rowb);
                LDMX4(al[mi][0], al[mi][1], al[mi][2], al[mi][3], bAl + rowb);
            }
            uint32_t bh[4][2], bl[4][2];
#pragma unroll
            for (int pr = 0; pr < 2; pr++) {
                const uint32_t rowb = (uint32_t)(pr * 16 * LDSROW * 2) + bLOff + kb;
                LDMX4(bh[pr * 2][0], bh[pr * 2][1], bh[pr * 2 + 1][0], bh[pr * 2 + 1][1], bWh + rowb);
                LDMX4(bl[pr * 2][0], bl[pr * 2][1], bl[pr * 2 + 1][0], bl[pr * 2 + 1][1], bWl + rowb);
            }
#pragma unroll
            for (int mi = 0; mi < 4; mi++)
#pragma unroll
                for (int nj = 0; nj < 4; nj++) {
                    MMA16816(acc[mi][nj], ah[mi], bh[nj]);
                    MMA16816(acc[mi][nj], al[mi], bh[nj]);
                    MMA16816(acc[mi][nj], ah[mi], bl[nj]);
                }
        }
        __syncthreads();
    }

    // epilogue
#pragma unroll
    for (int mi = 0; mi < 4; mi++) {
        const int r0 = bm0 + wm * 64 + mi * 16 + (lane >> 2);
#pragma unroll
        for (int nj = 0; nj < 4; nj++) {
            const int col = bn0 + wn * 32 + nj * 8 + (lane & 3) * 2;
            const float b0 = bias[col], b1 = bias[col + 1];
            float2 o0 = make_float2(acc[mi][nj][0] + b0, acc[mi][nj][1] + b1);
            float2 o1 = make_float2(acc[mi][nj][2] + b0, acc[mi][nj][3] + b1);
            *(float2*)(C + (size_t)r0 * H_ + col)       = o0;
            *(float2*)(C + (size_t)(r0 + 8) * H_ + col) = o1;
        }
    }
}

// ---------------------------------------------------------------------------
// Flash-style attention (unchanged, known-good). One block per
// (b, head, 64-row q-tile), 64 threads, one q-row per thread, online softmax.
// mask int32: nonzero -> key excluded. Scale = 1/32.
// ---------------------------------------------------------------------------
__global__ __launch_bounds__(64)
void attn_kernel(const float* __restrict__ Q, const float* __restrict__ Km,
                 const float* __restrict__ Vm,
                 const int* __restrict__ mask,
                 float* __restrict__ O)
{
    __shared__ float4 Ks[64][16];
    __shared__ float4 Vs[64][16];
    __shared__ int ms[64];

    const int t  = threadIdx.x;
    const int qt = blockIdx.x;
    const int h  = blockIdx.y;
    const int b  = blockIdx.z;
    const int hb = h * HD_;
    const int qr = qt * 64 + t;

    const float4* qp = (const float4*)(Q + ((size_t)(b * S_ + qr)) * H_ + hb);
    float4 q[16];
#pragma unroll
    for (int c = 0; c < 16; c++) q[c] = qp[c];

    float4 acc[16];
#pragma unroll
    for (int c = 0; c < 16; c++) acc[c] = make_float4(0.f, 0.f, 0.f, 0.f);
    float mmax = -3.0e38f;
    float l = 0.f;

    for (int kt = 0; kt < S_; kt += 64) {
        const float4* kp = (const float4*)(Km + ((size_t)(b * S_ + kt)) * H_ + hb);
        const float4* vp = (const float4*)(Vm + ((size_t)(b * S_ + kt)) * H_ + hb);
#pragma unroll
        for (int i = 0; i < 16; i++) {
            int idx = t + i * 64;
            int r = idx >> 4, c = idx & 15;
            Ks[r][c] = kp[(size_t)r * (H_ / 4) + c];
            Vs[r][c] = vp[(size_t)r * (H_ / 4) + c];
        }
        ms[t] = mask[(size_t)b * S_ + kt + t];
        __syncthreads();

        for (int kk = 0; kk < 64; kk++) {
            if (ms[kk]) continue;
            float4 s4 = make_float4(0.f, 0.f, 0.f, 0.f);
#pragma unroll
            for (int c = 0; c < 16; c++) {
                float4 kv = Ks[kk][c];
                s4.x += q[c].x * kv.x;
                s4.y += q[c].y * kv.y;
                s4.z += q[c].z * kv.z;
                s4.w += q[c].w * kv.w;
            }
            float s = (s4.x + s4.y + s4.z + s4.w) * 0.03125f;
            float p;
            if (s > mmax) {
                float f = __expf(mmax - s);
                l = l * f + 1.f;
#pragma unroll
                for (int c = 0; c < 16; c++) {
                    acc[c].x *= f; acc[c].y *= f; acc[c].z *= f; acc[c].w *= f;
                }
                mmax = s;
                p = 1.f;
            } else {
                p = __expf(s - mmax);
                l += p;
            }
#pragma unroll
            for (int c = 0; c < 16; c++) {
                float4 vv = Vs[kk][c];
                acc[c].x += p * vv.x;
                acc[c].y += p * vv.y;
                acc[c].z += p * vv.z;
                acc[c].w += p * vv.w;
            }
        }
        __syncthreads();
    }

    const float rl = 1.f / l;
    float4* op = (float4*)(O + ((size_t)(b * S_ + qr)) * H_ + hb);
#pragma unroll
    for (int c = 0; c < 16; c++) {
        float4 o;
        o.x = acc[c].x * rl;
        o.y = acc[c].y * rl;
        o.z = acc[c].z * rl;
        o.w = acc[c].w * rl;
        op[c] = o;
    }
}

// ---------------------------------------------------------------------------
extern "C" void kernel_launch(void* const* d_in, const int* in_sizes, int n_in,
                              void* d_out, int out_size)
{
    const float* query = (const float*)d_in[0];
    const float* key   = (const float*)d_in[1];
    const float* value = (const float*)d_in[2];
    const int*   mask  = (const int*)d_in[3];

    const int wb = (n_in >= 13) ? 5 : 4;
    const float* Wq = (const float*)d_in[wb + 0];
    const float* bq = (const float*)d_in[wb + 1];
    const float* Wk = (const float*)d_in[wb + 2];
    const float* bk = (const float*)d_in[wb + 3];
    const float* Wv = (const float*)d_in[wb + 4];
    const float* bv = (const float*)d_in[wb + 5];
    const float* Wo = (const float*)d_in[wb + 6];
    const float* bo = (const float*)d_in[wb + 7];
    float* out = (float*)d_out;

    float *dQ, *dK, *dV, *dA;
    cudaGetSymbolAddress((void**)&dQ, g_Q);
    cudaGetSymbolAddress((void**)&dK, g_K);
    cudaGetSymbolAddress((void**)&dV, g_V);
    cudaGetSymbolAddress((void**)&dA, g_A);

    dim3 ggrid(H_ / 128, MROWS / 128);   // (8, 64)
    gemm_tc<<<ggrid, 256>>>(query, Wq, bq, dQ);
    gemm_tc<<<ggrid, 256>>>(key,   Wk, bk, dK);
    gemm_tc<<<ggrid, 256>>>(value, Wv, bv, dV);

    dim3 agrid(S_ / 64, NH_, B_);        // (16, 16, 8)
    attn_kernel<<<agrid, 64>>>(dQ, dK, dV, mask, dA);

    gemm_tc<<<ggrid, 256>>>(dA, Wo, bo, out);
}